// round 15
// baseline (speedup 1.0000x reference)
#include <cuda_runtime.h>
#include <cstdint>
#include <math.h>

#define Bx 32
#define Tt 2048
#define Dd 256
#define Hh 256
#define Gg 512
#define NCTA 4
#define RTH 512

// Scratch (static device globals; no runtime allocation allowed)
__device__ float g_Gx[(size_t)Bx * Tt * Gg];   // x @ Wg_x + bg   [B*T, 512]
__device__ float g_Cx[(size_t)Bx * Tt * Hh];   // x @ Wc_x + bc   [B*T, 256]
__device__ float g_rnn[(size_t)Bx * Tt * Hh];  // GRU hidden outputs

__device__ __forceinline__ float sigmoidf_(float x) { return 1.f / (1.f + __expf(-x)); }
// fast tanh via single __expf: exact at +-inf, rel err ~1e-6
__device__ __forceinline__ float tanhf_fast(float x)
{
    float t = __expf(2.f * x);
    return 1.f - 2.f / (t + 1.f);
}

// ---------------------------------------------------------------------------
// f32x2 packed helpers (sm_103a FFMA2 — only reachable via PTX)
// ---------------------------------------------------------------------------
typedef unsigned long long u64t;
__device__ __forceinline__ u64t pack2_(float lo, float hi)
{ u64t r; asm("mov.b64 %0, {%1, %2};" : "=l"(r) : "f"(lo), "f"(hi)); return r; }
__device__ __forceinline__ void unpack2_(u64t v, float& lo, float& hi)
{ asm("mov.b64 {%0, %1}, %2;" : "=f"(lo), "=f"(hi) : "l"(v)); }
__device__ __forceinline__ u64t fma2_(u64t a, u64t b, u64t c)
{ u64t d; asm("fma.rn.f32x2 %0, %1, %2, %3;" : "=l"(d) : "l"(a), "l"(b), "l"(c)); return d; }
__device__ __forceinline__ u64t add2_(u64t a, u64t b)
{ u64t d; asm("add.rn.f32x2 %0, %1, %2;" : "=l"(d) : "l"(a), "l"(b)); return d; }

// cp.async helpers
__device__ __forceinline__ void cp_async16(uint32_t smem_addr, const void* gptr)
{
    asm volatile("cp.async.cg.shared.global [%0], [%1], 16;"
                 :: "r"(smem_addr), "l"(gptr) : "memory");
}
__device__ __forceinline__ void cp_commit_() { asm volatile("cp.async.commit_group;" ::: "memory"); }
__device__ __forceinline__ void cp_wait0_()  { asm volatile("cp.async.wait_group 0;" ::: "memory"); }

// ---------------------------------------------------------------------------
// Parallel GEMM: out[M,N] = A[M,256] @ W[0:256,N] + bias, optional sigmoid.
// r15: BK=32 (8 k-iters, half the barriers), B tile staged via cp.async
// (copies overlap compute; wait_group after compute), A reg-staged with STS
// after compute. 128x128 tile, 256 threads, 8x8/thread, f32x2 accumulators.
// Dynamic smem: 2 bufs x 32 x 132 x 2 arrays = 67,584 B.
// ---------------------------------------------------------------------------
#define GK 32
#define GPITCH 132
#define AS_OFF(buf,k,m) ((buf) * (GK * GPITCH) + (k) * GPITCH + (m))
#define BS_OFF(buf,k,n) (2 * GK * GPITCH + (buf) * (GK * GPITCH) + (k) * GPITCH + (n))
#define GEMM_SMEM_BYTES (4 * GK * GPITCH * 4)

template <int N, bool SIG>
__global__ void __launch_bounds__(256, 2) gemm128(
    const float* __restrict__ A, const float* __restrict__ W,
    const float* __restrict__ bias, float* __restrict__ out)
{
    extern __shared__ float smf[];
    const int tid = threadIdx.x;
    const int bm = blockIdx.x * 128;
    const int bn = blockIdx.y * 128;
    const int tx = tid & 15, ty = tid >> 4;        // 16x16 thread grid

    // A loader: thread covers row arow, k range ak..ak+15 (4 float4)
    const int arow = tid >> 1, ak = (tid & 1) * 16;
    // B loader: thread covers row brow (k), cols bc..bc+15 (4 cp.async 16B)
    const int brow = tid >> 3, bc = (tid & 7) * 16;

    u64t acc2[8][4];
#pragma unroll
    for (int i = 0; i < 8; i++)
#pragma unroll
        for (int j = 0; j < 4; j++) acc2[i][j] = 0ull;

    const float* aptr = A + (size_t)(bm + arow) * 256 + ak;
    const float* bptr = W + (size_t)brow * N + bn + bc;

    const uint32_t bs_dst0 = (uint32_t)__cvta_generic_to_shared(&smf[BS_OFF(0, brow, bc)]);
    const uint32_t bs_dst1 = (uint32_t)__cvta_generic_to_shared(&smf[BS_OFF(1, brow, bc)]);

    // ---- prologue: stage k-block 0 into buffer 0
    {
        float4 a0 = *(const float4*)(aptr + 0);
        float4 a1 = *(const float4*)(aptr + 4);
        float4 a2 = *(const float4*)(aptr + 8);
        float4 a3 = *(const float4*)(aptr + 12);
#pragma unroll
        for (int q = 0; q < 4; q++) cp_async16(bs_dst0 + q * 16, bptr + q * 4);
        cp_commit_();
        float av[16] = {a0.x,a0.y,a0.z,a0.w, a1.x,a1.y,a1.z,a1.w,
                        a2.x,a2.y,a2.z,a2.w, a3.x,a3.y,a3.z,a3.w};
#pragma unroll
        for (int e = 0; e < 16; e++) smf[AS_OFF(0, ak + e, arow)] = av[e];
        cp_wait0_();
    }
    __syncthreads();

    for (int it = 0; it < 8; it++) {
        const int cur = it & 1, nxt = cur ^ 1;
        float4 a0, a1, a2, a3;
        if (it < 7) {
            const int k1 = (it + 1) * GK;
            a0 = *(const float4*)(aptr + k1 + 0);
            a1 = *(const float4*)(aptr + k1 + 4);
            a2 = *(const float4*)(aptr + k1 + 8);
            a3 = *(const float4*)(aptr + k1 + 12);
            const float* bsrc = bptr + (size_t)k1 * N;
            const uint32_t bdst = nxt ? bs_dst1 : bs_dst0;
#pragma unroll
            for (int q = 0; q < 4; q++) cp_async16(bdst + q * 16, bsrc + q * 4);
            cp_commit_();
        }
#pragma unroll
        for (int kk = 0; kk < GK; kk++) {
            float4 av0 = *(const float4*)&smf[AS_OFF(cur, kk, ty * 8)];
            float4 av1 = *(const float4*)&smf[AS_OFF(cur, kk, ty * 8 + 4)];
            ulonglong2 bq0 = *(const ulonglong2*)&smf[BS_OFF(cur, kk, tx * 8)];
            ulonglong2 bq1 = *(const ulonglong2*)&smf[BS_OFF(cur, kk, tx * 8 + 4)];
            u64t bp[4] = {bq0.x, bq0.y, bq1.x, bq1.y};
            float a_[8] = {av0.x, av0.y, av0.z, av0.w, av1.x, av1.y, av1.z, av1.w};
#pragma unroll
            for (int i = 0; i < 8; i++) {
                u64t ad = pack2_(a_[i], a_[i]);
#pragma unroll
                for (int jp = 0; jp < 4; jp++)
                    acc2[i][jp] = fma2_(ad, bp[jp], acc2[i][jp]);
            }
        }
        if (it < 7) {
            float av[16] = {a0.x,a0.y,a0.z,a0.w, a1.x,a1.y,a1.z,a1.w,
                            a2.x,a2.y,a2.z,a2.w, a3.x,a3.y,a3.z,a3.w};
#pragma unroll
            for (int e = 0; e < 16; e++) smf[AS_OFF(nxt, ak + e, arow)] = av[e];
            cp_wait0_();
        }
        __syncthreads();
    }

    float4 bb0 = *(const float4*)&bias[bn + tx * 8];
    float4 bb1 = *(const float4*)&bias[bn + tx * 8 + 4];
    float bb[8] = {bb0.x, bb0.y, bb0.z, bb0.w, bb1.x, bb1.y, bb1.z, bb1.w};
#pragma unroll
    for (int i = 0; i < 8; i++) {
        int m = bm + ty * 8 + i;
        float v[8];
#pragma unroll
        for (int jp = 0; jp < 4; jp++) {
            float lo, hi; unpack2_(acc2[i][jp], lo, hi);
            v[2 * jp] = lo + bb[2 * jp];
            v[2 * jp + 1] = hi + bb[2 * jp + 1];
            if (SIG) { v[2 * jp] = sigmoidf_(v[2 * jp]); v[2 * jp + 1] = sigmoidf_(v[2 * jp + 1]); }
        }
        *(float4*)&out[(size_t)m * N + bn + tx * 8]     = make_float4(v[0], v[1], v[2], v[3]);
        *(float4*)&out[(size_t)m * N + bn + tx * 8 + 4] = make_float4(v[4], v[5], v[6], v[7]);
    }
}

// ---------------------------------------------------------------------------
// mbarrier / DSMEM async-store helpers
// ---------------------------------------------------------------------------
__device__ __forceinline__ uint32_t mapa_(uint32_t saddr, unsigned rank)
{
    uint32_t ra;
    asm volatile("mapa.shared::cluster.u32 %0, %1, %2;" : "=r"(ra) : "r"(saddr), "r"(rank));
    return ra;
}
__device__ __forceinline__ void st_async_tx(uint32_t raddr, float v, uint32_t rmbar)
{
    asm volatile("st.async.shared::cluster.mbarrier::complete_tx::bytes.b32 [%0], %1, [%2];"
                 :: "r"(raddr), "r"(__float_as_uint(v)), "r"(rmbar) : "memory");
}
__device__ __forceinline__ void mbar_init_(uint32_t mbar, uint32_t cnt)
{
    asm volatile("mbarrier.init.shared.b64 [%0], %1;" :: "r"(mbar), "r"(cnt) : "memory");
}
__device__ __forceinline__ void mbar_expect_tx_(uint32_t mbar, uint32_t bytes)
{
    asm volatile("mbarrier.arrive.expect_tx.shared.b64 _, [%0], %1;"
                 :: "r"(mbar), "r"(bytes) : "memory");
}
__device__ __forceinline__ void mbar_wait_parity_(uint32_t mbar, uint32_t parity)
{
    uint32_t done;
    asm volatile(
        "{\n\t.reg .pred p;\n\t"
        "mbarrier.try_wait.parity.acquire.cta.shared::cta.b64 p, [%1], %2;\n\t"
        "selp.b32 %0, 1, 0, p;\n\t}"
        : "=r"(done) : "r"(mbar), "r"(parity) : "memory");
    if (!done) {
        asm volatile(
            "{\n\t.reg .pred P1;\n\t"
            "WL_%=:\n\t"
            "mbarrier.try_wait.parity.acquire.cta.shared::cta.b64 P1, [%0], %1, 0x989680;\n\t"
            "@P1 bra.uni WD_%=;\n\t"
            "bra.uni WL_%=;\n\t"
            "WD_%=:\n\t}"
            :: "r"(mbar), "r"(parity) : "memory");
    }
}
__device__ __forceinline__ void cluster_sync_()
{
    asm volatile("barrier.cluster.arrive.aligned;" ::: "memory");
    asm volatile("barrier.cluster.wait.aligned;" ::: "memory");
}

// SMEM float offsets (keep 8B alignment for all f32x2/mbarrier regions)
#define OFF_WCT 0                  // cand weights transposed [256 cols][66 pad]
#define OFF_H   16896              // h slice [64]
#define OFF_RH  16960              // r*h slice [64]
#define OFF_U   17024              // u slice [64]
#define OFF_GP  17088              // gate partials [4 src][128] (coalesced st.async)
#define OFF_CP  17600              // cand partials [8 src][64]
#define OFF_MB  18112              // 2 mbarriers (2 floats each)
#define SMEM_FLOATS 18120
#define SMEM_BYTES (SMEM_FLOATS * 4)

// ---------------------------------------------------------------------------
// Recurrence — EXACT round-13 structure (best measured 3,194us config) with
// ONE edit: tanhf -> tanhf_fast (single __expf). Cand weights half-reg /
// half-smem; gate weights fully register-resident; st.async+mbarrier comm.
// ---------------------------------------------------------------------------
__global__ void __cluster_dims__(NCTA, 1, 1) __launch_bounds__(RTH, 1)
gru_rec(const float* __restrict__ Wg, const float* __restrict__ Wc)
{
    extern __shared__ float sm[];
    float* sWcT = sm + OFF_WCT;
    float* sh   = sm + OFF_H;
    float* srh  = sm + OFF_RH;
    float* su   = sm + OFF_U;
    float* sgp  = sm + OFF_GP;
    float* scp  = sm + OFF_CP;

    const int tid = threadIdx.x;
    unsigned rank;
    asm("mov.u32 %0, %%cluster_ctarank;" : "=r"(rank));
    const int j = (int)rank;
    const int b = blockIdx.x >> 2;

    const uint32_t gmb = (uint32_t)__cvta_generic_to_shared(sm + OFF_MB);
    const uint32_t cmb = (uint32_t)__cvta_generic_to_shared(sm + OFF_MB + 2);

    if (tid == 0) { mbar_init_(gmb, 1); mbar_init_(cmb, 1); }

    // ---- gate weight registers, packed row-pairs: thread = gate col `tid`,
    //      rows 256 + j*64 + (2i, 2i+1)
    u64t wg2[32];
#pragma unroll
    for (int i = 0; i < 32; i++) {
        float w0 = Wg[(size_t)(256 + j * 64 + 2 * i) * 512 + tid];
        float w1 = Wg[(size_t)(256 + j * 64 + 2 * i + 1) * 512 + tid];
        wg2[i] = pack2_(w0, w1);
    }

    // cand thread mapping
    const int c = tid & 255;
    const int s = tid >> 8;

    // ---- cand weight registers: rows s*32 + (2i, 2i+1), i = 0..7 (16 rows)
    u64t wc2[8];
#pragma unroll
    for (int i = 0; i < 8; i++) {
        int row = 256 + j * 64 + s * 32 + 2 * i;
        wc2[i] = pack2_(Wc[(size_t)row * 256 + c],
                        Wc[(size_t)(row + 1) * 256 + c]);
    }

    // ---- stage candidate weights transposed: sWcT[cc*66 + r] = Wc_h[row r, col cc]
    for (int idx = tid; idx < 64 * 256; idx += RTH) {
        int cc = idx & 255, r = idx >> 8;
        sWcT[cc * 66 + r] = Wc[(size_t)(256 + j * 64 + r) * 256 + cc];
    }
    if (tid < 64) sh[tid] = 0.f;
    __syncthreads();
    cluster_sync_();   // mbarriers + weights visible cluster-wide before any st.async

    const float* gGx = g_Gx + (size_t)b * Tt * Gg;
    const float* gCx = g_Cx + (size_t)b * Tt * Hh;
    float* grnn = g_rnn + (size_t)b * Tt * Hh;

    // gate column -> owner rank + local slot; precompute remote addrs (loop-invariant)
    const int gk = (tid < 256) ? (tid >> 6) : ((tid >> 6) & 3);
    const int gl = (tid < 256) ? (tid & 63) : (64 + (tid & 63));
    const uint32_t gp_rem  = mapa_((uint32_t)__cvta_generic_to_shared(&sgp[j * 128 + gl]), (unsigned)gk);
    const uint32_t gmb_rem = mapa_(gmb, (unsigned)gk);

    // cand: thread = (col c, row-half s)
    const int ck = c >> 6;
    const uint32_t cp_rem  = mapa_((uint32_t)__cvta_generic_to_shared(&scp[(j * 2 + s) * 64 + (c & 63)]), (unsigned)ck);
    const uint32_t cmb_rem = mapa_(cmb, (unsigned)ck);
    const float* wcbase = sWcT + c * 66 + s * 32;
    const float* rhbase = srh + s * 32;

    const int gxcol = (tid < 64) ? (j * 64 + tid) : (256 + j * 64 + (tid - 64));

    float gx = (tid < 128) ? gGx[gxcol] : 0.f;
    float cx = (tid < 64)  ? gCx[j * 64 + tid] : 0.f;

    for (int t = 0; t < Tt; t++) {
        const uint32_t ph = (uint32_t)(t & 1);
        if (tid == 0) mbar_expect_tx_(gmb, NCTA * 128 * 4);

        // ===== gate partial GEMV (64 own rows x 1 col), FFMA2, 2 chains =====
        {
            u64t accA = 0ull, accB = 0ull;
            const u64t* hp2 = (const u64t*)sh;
#pragma unroll
            for (int i = 0; i < 16; i++) {
                accA = fma2_(hp2[2 * i],     wg2[2 * i],     accA);
                accB = fma2_(hp2[2 * i + 1], wg2[2 * i + 1], accB);
            }
            u64t acc2 = add2_(accA, accB);
            float lo, hi; unpack2_(acc2, lo, hi);
            st_async_tx(gp_rem, lo + hi, gmb_rem);
        }
        // only the consumers of gate partials need the acquire-wait;
        // everyone else is ordered by the __syncthreads below
        if (tid < 128) mbar_wait_parity_(gmb, ph);
        if (tid == 0) mbar_expect_tx_(cmb, NCTA * 128 * 4);

        // ===== gate reduce + r*h / u (local) ================================
        if (tid < 128) {
            float sv = gx + sgp[tid] + sgp[128 + tid] + sgp[256 + tid] + sgp[384 + tid];
            float val = sigmoidf_(sv);
            if (tid < 64) srh[tid] = val * sh[tid];
            else          su[tid - 64] = val;
        }
        if (tid < 128 && t + 1 < Tt)
            gx = gGx[(size_t)(t + 1) * Gg + gxcol];          // prefetch
        __syncthreads();   // srh ready for all threads

        // ===== cand partial GEMV (32 rows x 1 col), FFMA2:
        //       rows 0..15 from REGISTER weights, rows 16..31 from smem ======
        {
            u64t accA = 0ull, accB = 0ull;
            const u64t* rp2 = (const u64t*)rhbase;
            const u64t* wp2 = (const u64t*)wcbase;
#pragma unroll
            for (int i = 0; i < 8; i++) {
                accA = fma2_(rp2[i],     wc2[i],     accA);   // reg half
                accB = fma2_(rp2[8 + i], wp2[8 + i], accB);   // smem half
            }
            u64t acc2 = add2_(accA, accB);
            float lo, hi; unpack2_(acc2, lo, hi);
            st_async_tx(cp_rem, lo + hi, cmb_rem);
        }
        if (tid < 64) mbar_wait_parity_(cmb, ph);           // cand consumers only

        // ===== cand reduce + h update (all local) ===========================
        if (tid < 64) {
            float cc = cx;
#pragma unroll
            for (int m = 0; m < 8; m++) cc += scp[m * 64 + tid];
            float cv = tanhf_fast(cc);
            float u = su[tid];
            float hn = u * sh[tid] + (1.f - u) * cv;
            sh[tid] = hn;
            grnn[(size_t)t * Hh + j * 64 + tid] = hn;
        }
        if (tid < 64 && t + 1 < Tt)
            cx = gCx[(size_t)(t + 1) * Hh + j * 64 + tid];   // prefetch
        __syncthreads();   // sh update visible before next gate GEMV
    }
    cluster_sync_();       // keep peers resident until all deliveries consumed
}

// ---------------------------------------------------------------------------
extern "C" void kernel_launch(void* const* d_in, const int* in_sizes, int n_in,
                              void* d_out, int out_size)
{
    const float* x  = (const float*)d_in[0];
    const float* Wg = (const float*)d_in[1];
    const float* bg = (const float*)d_in[2];
    const float* Wc = (const float*)d_in[3];
    const float* bc = (const float*)d_in[4];
    const float* Wp = (const float*)d_in[5];
    const float* bp = (const float*)d_in[6];
    float* out = (float*)d_out;

    float *pGx = nullptr, *pCx = nullptr, *prnn = nullptr;
    cudaGetSymbolAddress((void**)&pGx, g_Gx);
    cudaGetSymbolAddress((void**)&pCx, g_Cx);
    cudaGetSymbolAddress((void**)&prnn, g_rnn);
    cudaFuncSetAttribute(gru_rec, cudaFuncAttributeMaxDynamicSharedMemorySize, SMEM_BYTES);
    cudaFuncSetAttribute(gemm128<512, false>, cudaFuncAttributeMaxDynamicSharedMemorySize, GEMM_SMEM_BYTES);
    cudaFuncSetAttribute(gemm128<256, false>, cudaFuncAttributeMaxDynamicSharedMemorySize, GEMM_SMEM_BYTES);
    cudaFuncSetAttribute(gemm128<256, true>,  cudaFuncAttributeMaxDynamicSharedMemorySize, GEMM_SMEM_BYTES);

    // Parallel precompute of x-projections (fold biases in)
    gemm128<512, false><<<dim3(512, 4), 256, GEMM_SMEM_BYTES>>>(x, Wg, bg, pGx);
    gemm128<256, false><<<dim3(512, 2), 256, GEMM_SMEM_BYTES>>>(x, Wc, bc, pCx);

    // Sequential recurrence: 32 clusters x 4 CTAs, 1 batch per cluster
    gru_rec<<<128, RTH, SMEM_BYTES>>>(Wg, Wc);

    // Projection + sigmoid
    gemm128<256, true><<<dim3(512, 2), 256, GEMM_SMEM_BYTES>>>(prnn, Wp, bp, out);
}

// round 16
// speedup vs baseline: 1.0081x; 1.0081x over previous
#include <cuda_runtime.h>
#include <cstdint>
#include <math.h>

#define Bx 32
#define Tt 2048
#define Dd 256
#define Hh 256
#define Gg 512
#define NCTA 4
#define RTH 512

// Scratch (static device globals; no runtime allocation allowed)
__device__ float g_Gx[(size_t)Bx * Tt * Gg];   // x @ Wg_x + bg   [B*T, 512]
__device__ float g_Cx[(size_t)Bx * Tt * Hh];   // x @ Wc_x + bc   [B*T, 256]
__device__ float g_rnn[(size_t)Bx * Tt * Hh];  // GRU hidden outputs

__device__ __forceinline__ float sigmoidf_(float x) { return 1.f / (1.f + __expf(-x)); }

// ---------------------------------------------------------------------------
// f32x2 packed helpers (sm_103a FFMA2 — only reachable via PTX)
// ---------------------------------------------------------------------------
typedef unsigned long long u64t;
__device__ __forceinline__ u64t pack2_(float lo, float hi)
{ u64t r; asm("mov.b64 %0, {%1, %2};" : "=l"(r) : "f"(lo), "f"(hi)); return r; }
__device__ __forceinline__ void unpack2_(u64t v, float& lo, float& hi)
{ asm("mov.b64 {%0, %1}, %2;" : "=f"(lo), "=f"(hi) : "l"(v)); }
__device__ __forceinline__ u64t fma2_(u64t a, u64t b, u64t c)
{ u64t d; asm("fma.rn.f32x2 %0, %1, %2, %3;" : "=l"(d) : "l"(a), "l"(b), "l"(c)); return d; }
__device__ __forceinline__ u64t add2_(u64t a, u64t b)
{ u64t d; asm("add.rn.f32x2 %0, %1, %2;" : "=l"(d) : "l"(a), "l"(b)); return d; }

// cp.async helpers
__device__ __forceinline__ void cp_async16(uint32_t smem_addr, const void* gptr)
{
    asm volatile("cp.async.cg.shared.global [%0], [%1], 16;"
                 :: "r"(smem_addr), "l"(gptr) : "memory");
}
__device__ __forceinline__ void cp_commit_() { asm volatile("cp.async.commit_group;" ::: "memory"); }
__device__ __forceinline__ void cp_wait0_()  { asm volatile("cp.async.wait_group 0;" ::: "memory"); }

// ---------------------------------------------------------------------------
// GEMM core (r15 body): 128x128 tile, BK=32, 256 threads, 8x8/thread f32x2
// accumulators, B via cp.async double-buffer, A reg-staged. Runtime N.
// ---------------------------------------------------------------------------
#define GK 32
#define GPITCH 132
#define AS_OFF(buf,k,m) ((buf) * (GK * GPITCH) + (k) * GPITCH + (m))
#define BS_OFF(buf,k,n) (2 * GK * GPITCH + (buf) * (GK * GPITCH) + (k) * GPITCH + (n))
#define GEMM_SMEM_BYTES (4 * GK * GPITCH * 4)

template <bool SIG>
__device__ __forceinline__ void gemm_body(
    const float* __restrict__ A, const float* __restrict__ W,
    const float* __restrict__ bias, float* __restrict__ out,
    int N, int bm, int bn, float* smf)
{
    const int tid = threadIdx.x;
    const int tx = tid & 15, ty = tid >> 4;        // 16x16 thread grid
    const int arow = tid >> 1, ak = (tid & 1) * 16;
    const int brow = tid >> 3, bc = (tid & 7) * 16;

    u64t acc2[8][4];
#pragma unroll
    for (int i = 0; i < 8; i++)
#pragma unroll
        for (int j = 0; j < 4; j++) acc2[i][j] = 0ull;

    const float* aptr = A + (size_t)(bm + arow) * 256 + ak;
    const float* bptr = W + (size_t)brow * N + bn + bc;

    const uint32_t bs_dst0 = (uint32_t)__cvta_generic_to_shared(&smf[BS_OFF(0, brow, bc)]);
    const uint32_t bs_dst1 = (uint32_t)__cvta_generic_to_shared(&smf[BS_OFF(1, brow, bc)]);

    {
        float4 a0 = *(const float4*)(aptr + 0);
        float4 a1 = *(const float4*)(aptr + 4);
        float4 a2 = *(const float4*)(aptr + 8);
        float4 a3 = *(const float4*)(aptr + 12);
#pragma unroll
        for (int q = 0; q < 4; q++) cp_async16(bs_dst0 + q * 16, bptr + q * 4);
        cp_commit_();
        float av[16] = {a0.x,a0.y,a0.z,a0.w, a1.x,a1.y,a1.z,a1.w,
                        a2.x,a2.y,a2.z,a2.w, a3.x,a3.y,a3.z,a3.w};
#pragma unroll
        for (int e = 0; e < 16; e++) smf[AS_OFF(0, ak + e, arow)] = av[e];
        cp_wait0_();
    }
    __syncthreads();

    for (int it = 0; it < 8; it++) {
        const int cur = it & 1, nxt = cur ^ 1;
        float4 a0, a1, a2, a3;
        if (it < 7) {
            const int k1 = (it + 1) * GK;
            a0 = *(const float4*)(aptr + k1 + 0);
            a1 = *(const float4*)(aptr + k1 + 4);
            a2 = *(const float4*)(aptr + k1 + 8);
            a3 = *(const float4*)(aptr + k1 + 12);
            const float* bsrc = bptr + (size_t)k1 * N;
            const uint32_t bdst = nxt ? bs_dst1 : bs_dst0;
#pragma unroll
            for (int q = 0; q < 4; q++) cp_async16(bdst + q * 16, bsrc + q * 4);
            cp_commit_();
        }
#pragma unroll
        for (int kk = 0; kk < GK; kk++) {
            float4 av0 = *(const float4*)&smf[AS_OFF(cur, kk, ty * 8)];
            float4 av1 = *(const float4*)&smf[AS_OFF(cur, kk, ty * 8 + 4)];
            ulonglong2 bq0 = *(const ulonglong2*)&smf[BS_OFF(cur, kk, tx * 8)];
            ulonglong2 bq1 = *(const ulonglong2*)&smf[BS_OFF(cur, kk, tx * 8 + 4)];
            u64t bp[4] = {bq0.x, bq0.y, bq1.x, bq1.y};
            float a_[8] = {av0.x, av0.y, av0.z, av0.w, av1.x, av1.y, av1.z, av1.w};
#pragma unroll
            for (int i = 0; i < 8; i++) {
                u64t ad = pack2_(a_[i], a_[i]);
#pragma unroll
                for (int jp = 0; jp < 4; jp++)
                    acc2[i][jp] = fma2_(ad, bp[jp], acc2[i][jp]);
            }
        }
        if (it < 7) {
            float av[16] = {a0.x,a0.y,a0.z,a0.w, a1.x,a1.y,a1.z,a1.w,
                            a2.x,a2.y,a2.z,a2.w, a3.x,a3.y,a3.z,a3.w};
#pragma unroll
            for (int e = 0; e < 16; e++) smf[AS_OFF(nxt, ak + e, arow)] = av[e];
            cp_wait0_();
        }
        __syncthreads();
    }

    float4 bb0 = *(const float4*)&bias[bn + tx * 8];
    float4 bb1 = *(const float4*)&bias[bn + tx * 8 + 4];
    float bb[8] = {bb0.x, bb0.y, bb0.z, bb0.w, bb1.x, bb1.y, bb1.z, bb1.w};
#pragma unroll
    for (int i = 0; i < 8; i++) {
        int m = bm + ty * 8 + i;
        float v[8];
#pragma unroll
        for (int jp = 0; jp < 4; jp++) {
            float lo, hi; unpack2_(acc2[i][jp], lo, hi);
            v[2 * jp] = lo + bb[2 * jp];
            v[2 * jp + 1] = hi + bb[2 * jp + 1];
            if (SIG) { v[2 * jp] = sigmoidf_(v[2 * jp]); v[2 * jp + 1] = sigmoidf_(v[2 * jp + 1]); }
        }
        *(float4*)&out[(size_t)m * N + bn + tx * 8]     = make_float4(v[0], v[1], v[2], v[3]);
        *(float4*)&out[(size_t)m * N + bn + tx * 8 + 4] = make_float4(v[4], v[5], v[6], v[7]);
    }
}

// Fused Gx+Cx kernel: blockIdx.x selects output (0..3 -> Gx tile, 4..5 -> Cx
// tile); blockIdx.y = bm panel. bn-major grid => a wave spans all bn tiles of
// few bm panels, so the A panel is read from DRAM once and reused via L2.
__global__ void __launch_bounds__(256, 2) gemm_fused(
    const float* __restrict__ A,
    const float* __restrict__ Wg, const float* __restrict__ bg,
    const float* __restrict__ Wc, const float* __restrict__ bc,
    float* __restrict__ Gx, float* __restrict__ Cx)
{
    extern __shared__ float smf[];
    const int bnG = blockIdx.x;
    const int bm = blockIdx.y * 128;
    if (bnG < 4)
        gemm_body<false>(A, Wg, bg, Gx, 512, bm, bnG * 128, smf);
    else
        gemm_body<false>(A, Wc, bc, Cx, 256, bm, (bnG - 4) * 128, smf);
}

// Projection kernel (sigmoid), bn-major grid dim3(2, 512)
__global__ void __launch_bounds__(256, 2) gemm_proj(
    const float* __restrict__ A, const float* __restrict__ W,
    const float* __restrict__ bias, float* __restrict__ out)
{
    extern __shared__ float smf[];
    gemm_body<true>(A, W, bias, out, 256, blockIdx.y * 128, blockIdx.x * 128, smf);
}

// ---------------------------------------------------------------------------
// mbarrier / DSMEM async-store helpers
// ---------------------------------------------------------------------------
__device__ __forceinline__ uint32_t mapa_(uint32_t saddr, unsigned rank)
{
    uint32_t ra;
    asm volatile("mapa.shared::cluster.u32 %0, %1, %2;" : "=r"(ra) : "r"(saddr), "r"(rank));
    return ra;
}
__device__ __forceinline__ void st_async_tx(uint32_t raddr, float v, uint32_t rmbar)
{
    asm volatile("st.async.shared::cluster.mbarrier::complete_tx::bytes.b32 [%0], %1, [%2];"
                 :: "r"(raddr), "r"(__float_as_uint(v)), "r"(rmbar) : "memory");
}
__device__ __forceinline__ void mbar_init_(uint32_t mbar, uint32_t cnt)
{
    asm volatile("mbarrier.init.shared.b64 [%0], %1;" :: "r"(mbar), "r"(cnt) : "memory");
}
__device__ __forceinline__ void mbar_expect_tx_(uint32_t mbar, uint32_t bytes)
{
    asm volatile("mbarrier.arrive.expect_tx.shared.b64 _, [%0], %1;"
                 :: "r"(mbar), "r"(bytes) : "memory");
}
__device__ __forceinline__ void mbar_wait_parity_(uint32_t mbar, uint32_t parity)
{
    uint32_t done;
    asm volatile(
        "{\n\t.reg .pred p;\n\t"
        "mbarrier.try_wait.parity.acquire.cta.shared::cta.b64 p, [%1], %2;\n\t"
        "selp.b32 %0, 1, 0, p;\n\t}"
        : "=r"(done) : "r"(mbar), "r"(parity) : "memory");
    if (!done) {
        asm volatile(
            "{\n\t.reg .pred P1;\n\t"
            "WL_%=:\n\t"
            "mbarrier.try_wait.parity.acquire.cta.shared::cta.b64 P1, [%0], %1, 0x989680;\n\t"
            "@P1 bra.uni WD_%=;\n\t"
            "bra.uni WL_%=;\n\t"
            "WD_%=:\n\t}"
            :: "r"(mbar), "r"(parity) : "memory");
    }
}
__device__ __forceinline__ void cluster_sync_()
{
    asm volatile("barrier.cluster.arrive.aligned;" ::: "memory");
    asm volatile("barrier.cluster.wait.aligned;" ::: "memory");
}

// SMEM float offsets (keep 8B alignment for all f32x2/mbarrier regions)
#define OFF_WCT 0                  // cand weights transposed [256 cols][66 pad]
#define OFF_H   16896              // h slice [64]
#define OFF_RH  16960              // r*h slice [64]
#define OFF_U   17024              // u slice [64]
#define OFF_GP  17088              // gate partials [4 src][128] (coalesced st.async)
#define OFF_CP  17600              // cand partials [8 src][64]
#define OFF_MB  18112              // 2 mbarriers (2 floats each)
#define SMEM_FLOATS 18120
#define SMEM_BYTES (SMEM_FLOATS * 4)

// ---------------------------------------------------------------------------
// Recurrence — EXACT round-13 structure (best measured 3,194us): cand weights
// half-reg/half-smem, gate weights register-resident, st.async+mbarrier comm,
// library tanhf (r15's fast tanh reverted: it was slower than the HW path).
// ---------------------------------------------------------------------------
__global__ void __cluster_dims__(NCTA, 1, 1) __launch_bounds__(RTH, 1)
gru_rec(const float* __restrict__ Wg, const float* __restrict__ Wc)
{
    extern __shared__ float sm[];
    float* sWcT = sm + OFF_WCT;
    float* sh   = sm + OFF_H;
    float* srh  = sm + OFF_RH;
    float* su   = sm + OFF_U;
    float* sgp  = sm + OFF_GP;
    float* scp  = sm + OFF_CP;

    const int tid = threadIdx.x;
    unsigned rank;
    asm("mov.u32 %0, %%cluster_ctarank;" : "=r"(rank));
    const int j = (int)rank;
    const int b = blockIdx.x >> 2;

    const uint32_t gmb = (uint32_t)__cvta_generic_to_shared(sm + OFF_MB);
    const uint32_t cmb = (uint32_t)__cvta_generic_to_shared(sm + OFF_MB + 2);

    if (tid == 0) { mbar_init_(gmb, 1); mbar_init_(cmb, 1); }

    // ---- gate weight registers, packed row-pairs: thread = gate col `tid`,
    //      rows 256 + j*64 + (2i, 2i+1)
    u64t wg2[32];
#pragma unroll
    for (int i = 0; i < 32; i++) {
        float w0 = Wg[(size_t)(256 + j * 64 + 2 * i) * 512 + tid];
        float w1 = Wg[(size_t)(256 + j * 64 + 2 * i + 1) * 512 + tid];
        wg2[i] = pack2_(w0, w1);
    }

    // cand thread mapping
    const int c = tid & 255;
    const int s = tid >> 8;

    // ---- cand weight registers: rows s*32 + (2i, 2i+1), i = 0..7 (16 rows)
    u64t wc2[8];
#pragma unroll
    for (int i = 0; i < 8; i++) {
        int row = 256 + j * 64 + s * 32 + 2 * i;
        wc2[i] = pack2_(Wc[(size_t)row * 256 + c],
                        Wc[(size_t)(row + 1) * 256 + c]);
    }

    // ---- stage candidate weights transposed: sWcT[cc*66 + r] = Wc_h[row r, col cc]
    for (int idx = tid; idx < 64 * 256; idx += RTH) {
        int cc = idx & 255, r = idx >> 8;
        sWcT[cc * 66 + r] = Wc[(size_t)(256 + j * 64 + r) * 256 + cc];
    }
    if (tid < 64) sh[tid] = 0.f;
    __syncthreads();
    cluster_sync_();   // mbarriers + weights visible cluster-wide before any st.async

    const float* gGx = g_Gx + (size_t)b * Tt * Gg;
    const float* gCx = g_Cx + (size_t)b * Tt * Hh;
    float* grnn = g_rnn + (size_t)b * Tt * Hh;

    // gate column -> owner rank + local slot; precompute remote addrs (loop-invariant)
    const int gk = (tid < 256) ? (tid >> 6) : ((tid >> 6) & 3);
    const int gl = (tid < 256) ? (tid & 63) : (64 + (tid & 63));
    const uint32_t gp_rem  = mapa_((uint32_t)__cvta_generic_to_shared(&sgp[j * 128 + gl]), (unsigned)gk);
    const uint32_t gmb_rem = mapa_(gmb, (unsigned)gk);

    // cand: thread = (col c, row-half s)
    const int ck = c >> 6;
    const uint32_t cp_rem  = mapa_((uint32_t)__cvta_generic_to_shared(&scp[(j * 2 + s) * 64 + (c & 63)]), (unsigned)ck);
    const uint32_t cmb_rem = mapa_(cmb, (unsigned)ck);
    const float* wcbase = sWcT + c * 66 + s * 32;
    const float* rhbase = srh + s * 32;

    const int gxcol = (tid < 64) ? (j * 64 + tid) : (256 + j * 64 + (tid - 64));

    float gx = (tid < 128) ? gGx[gxcol] : 0.f;
    float cx = (tid < 64)  ? gCx[j * 64 + tid] : 0.f;

    for (int t = 0; t < Tt; t++) {
        const uint32_t ph = (uint32_t)(t & 1);
        if (tid == 0) mbar_expect_tx_(gmb, NCTA * 128 * 4);

        // ===== gate partial GEMV (64 own rows x 1 col), FFMA2, 2 chains =====
        {
            u64t accA = 0ull, accB = 0ull;
            const u64t* hp2 = (const u64t*)sh;
#pragma unroll
            for (int i = 0; i < 16; i++) {
                accA = fma2_(hp2[2 * i],     wg2[2 * i],     accA);
                accB = fma2_(hp2[2 * i + 1], wg2[2 * i + 1], accB);
            }
            u64t acc2 = add2_(accA, accB);
            float lo, hi; unpack2_(acc2, lo, hi);
            st_async_tx(gp_rem, lo + hi, gmb_rem);
        }
        // only the consumers of gate partials need the acquire-wait;
        // everyone else is ordered by the __syncthreads below
        if (tid < 128) mbar_wait_parity_(gmb, ph);
        if (tid == 0) mbar_expect_tx_(cmb, NCTA * 128 * 4);

        // ===== gate reduce + r*h / u (local) ================================
        if (tid < 128) {
            float sv = gx + sgp[tid] + sgp[128 + tid] + sgp[256 + tid] + sgp[384 + tid];
            float val = sigmoidf_(sv);
            if (tid < 64) srh[tid] = val * sh[tid];
            else          su[tid - 64] = val;
        }
        if (tid < 128 && t + 1 < Tt)
            gx = gGx[(size_t)(t + 1) * Gg + gxcol];          // prefetch
        __syncthreads();   // srh ready for all threads

        // ===== cand partial GEMV (32 rows x 1 col), FFMA2:
        //       rows 0..15 from REGISTER weights, rows 16..31 from smem ======
        {
            u64t accA = 0ull, accB = 0ull;
            const u64t* rp2 = (const u64t*)rhbase;
            const u64t* wp2 = (const u64t*)wcbase;
#pragma unroll
            for (int i = 0; i < 8; i++) {
                accA = fma2_(rp2[i],     wc2[i],     accA);   // reg half
                accB = fma2_(rp2[8 + i], wp2[8 + i], accB);   // smem half
            }
            u64t acc2 = add2_(accA, accB);
            float lo, hi; unpack2_(acc2, lo, hi);
            st_async_tx(cp_rem, lo + hi, cmb_rem);
        }
        if (tid < 64) mbar_wait_parity_(cmb, ph);           // cand consumers only

        // ===== cand reduce + h update (all local) ===========================
        if (tid < 64) {
            float cc = cx;
#pragma unroll
            for (int m = 0; m < 8; m++) cc += scp[m * 64 + tid];
            float cv = tanhf(cc);
            float u = su[tid];
            float hn = u * sh[tid] + (1.f - u) * cv;
            sh[tid] = hn;
            grnn[(size_t)t * Hh + j * 64 + tid] = hn;
        }
        if (tid < 64 && t + 1 < Tt)
            cx = gCx[(size_t)(t + 1) * Hh + j * 64 + tid];   // prefetch
        __syncthreads();   // sh update visible before next gate GEMV
    }
    cluster_sync_();       // keep peers resident until all deliveries consumed
}

// ---------------------------------------------------------------------------
extern "C" void kernel_launch(void* const* d_in, const int* in_sizes, int n_in,
                              void* d_out, int out_size)
{
    const float* x  = (const float*)d_in[0];
    const float* Wg = (const float*)d_in[1];
    const float* bg = (const float*)d_in[2];
    const float* Wc = (const float*)d_in[3];
    const float* bc = (const float*)d_in[4];
    const float* Wp = (const float*)d_in[5];
    const float* bp = (const float*)d_in[6];
    float* out = (float*)d_out;

    float *pGx = nullptr, *pCx = nullptr, *prnn = nullptr;
    cudaGetSymbolAddress((void**)&pGx, g_Gx);
    cudaGetSymbolAddress((void**)&pCx, g_Cx);
    cudaGetSymbolAddress((void**)&prnn, g_rnn);
    cudaFuncSetAttribute(gru_rec, cudaFuncAttributeMaxDynamicSharedMemorySize, SMEM_BYTES);
    cudaFuncSetAttribute(gemm_fused, cudaFuncAttributeMaxDynamicSharedMemorySize, GEMM_SMEM_BYTES);
    cudaFuncSetAttribute(gemm_proj,  cudaFuncAttributeMaxDynamicSharedMemorySize, GEMM_SMEM_BYTES);

    // Fused x-projections (x read once; bn-major grid for L2 reuse of A)
    gemm_fused<<<dim3(6, 512), 256, GEMM_SMEM_BYTES>>>(x, Wg, bg, Wc, bc, pGx, pCx);

    // Sequential recurrence: 32 clusters x 4 CTAs, 1 batch per cluster
    gru_rec<<<128, RTH, SMEM_BYTES>>>(Wg, Wc);

    // Projection + sigmoid
    gemm_proj<<<dim3(2, 512), 256, GEMM_SMEM_BYTES>>>(prnn, Wp, bp, out);
}

// round 17
// speedup vs baseline: 1.0626x; 1.0541x over previous
#include <cuda_runtime.h>
#include <cstdint>
#include <math.h>

#define Bx 32
#define Tt 2048
#define Dd 256
#define Hh 256
#define Gg 512
#define NCTA 4
#define RTH 512

// Scratch (static device globals; no runtime allocation allowed)
__device__ float g_Gx[(size_t)Bx * Tt * Gg];   // x @ Wg_x + bg   [B*T, 512]
__device__ float g_Cx[(size_t)Bx * Tt * Hh];   // x @ Wc_x + bc   [B*T, 256]
__device__ float g_rnn[(size_t)Bx * Tt * Hh];  // GRU hidden outputs

__device__ __forceinline__ float sigmoidf_(float x) { return 1.f / (1.f + __expf(-x)); }

// single-MUFU approximations (MUFU.TANH, rel err ~1.6e-5; budget is 1e-3)
__device__ __forceinline__ float tanh_ap(float x)
{ float y; asm("tanh.approx.f32 %0, %1;" : "=f"(y) : "f"(x)); return y; }
__device__ __forceinline__ float sigmoid_ap(float x)
{ return fmaf(tanh_ap(0.5f * x), 0.5f, 0.5f); }

// ---------------------------------------------------------------------------
// f32x2 packed helpers (sm_103a FFMA2 — only reachable via PTX)
// ---------------------------------------------------------------------------
typedef unsigned long long u64t;
__device__ __forceinline__ u64t pack2_(float lo, float hi)
{ u64t r; asm("mov.b64 %0, {%1, %2};" : "=l"(r) : "f"(lo), "f"(hi)); return r; }
__device__ __forceinline__ void unpack2_(u64t v, float& lo, float& hi)
{ asm("mov.b64 {%0, %1}, %2;" : "=f"(lo), "=f"(hi) : "l"(v)); }
__device__ __forceinline__ u64t fma2_(u64t a, u64t b, u64t c)
{ u64t d; asm("fma.rn.f32x2 %0, %1, %2, %3;" : "=l"(d) : "l"(a), "l"(b), "l"(c)); return d; }
__device__ __forceinline__ u64t add2_(u64t a, u64t b)
{ u64t d; asm("add.rn.f32x2 %0, %1, %2;" : "=l"(d) : "l"(a), "l"(b)); return d; }

// cp.async helpers
__device__ __forceinline__ void cp_async16(uint32_t smem_addr, const void* gptr)
{
    asm volatile("cp.async.cg.shared.global [%0], [%1], 16;"
                 :: "r"(smem_addr), "l"(gptr) : "memory");
}
__device__ __forceinline__ void cp_commit_() { asm volatile("cp.async.commit_group;" ::: "memory"); }
__device__ __forceinline__ void cp_wait0_()  { asm volatile("cp.async.wait_group 0;" ::: "memory"); }

// ---------------------------------------------------------------------------
// GEMM core: 128x128 tile, BK=32, 256 threads, 8x8/thread f32x2 accumulators,
// B via cp.async double-buffer, A reg-staged. Runtime N.
// ---------------------------------------------------------------------------
#define GK 32
#define GPITCH 132
#define AS_OFF(buf,k,m) ((buf) * (GK * GPITCH) + (k) * GPITCH + (m))
#define BS_OFF(buf,k,n) (2 * GK * GPITCH + (buf) * (GK * GPITCH) + (k) * GPITCH + (n))
#define GEMM_SMEM_BYTES (4 * GK * GPITCH * 4)

template <bool SIG>
__device__ __forceinline__ void gemm_body(
    const float* __restrict__ A, const float* __restrict__ W,
    const float* __restrict__ bias, float* __restrict__ out,
    int N, int bm, int bn, float* smf)
{
    const int tid = threadIdx.x;
    const int tx = tid & 15, ty = tid >> 4;        // 16x16 thread grid
    const int arow = tid >> 1, ak = (tid & 1) * 16;
    const int brow = tid >> 3, bc = (tid & 7) * 16;

    u64t acc2[8][4];
#pragma unroll
    for (int i = 0; i < 8; i++)
#pragma unroll
        for (int j = 0; j < 4; j++) acc2[i][j] = 0ull;

    const float* aptr = A + (size_t)(bm + arow) * 256 + ak;
    const float* bptr = W + (size_t)brow * N + bn + bc;

    const uint32_t bs_dst0 = (uint32_t)__cvta_generic_to_shared(&smf[BS_OFF(0, brow, bc)]);
    const uint32_t bs_dst1 = (uint32_t)__cvta_generic_to_shared(&smf[BS_OFF(1, brow, bc)]);

    {
        float4 a0 = *(const float4*)(aptr + 0);
        float4 a1 = *(const float4*)(aptr + 4);
        float4 a2 = *(const float4*)(aptr + 8);
        float4 a3 = *(const float4*)(aptr + 12);
#pragma unroll
        for (int q = 0; q < 4; q++) cp_async16(bs_dst0 + q * 16, bptr + q * 4);
        cp_commit_();
        float av[16] = {a0.x,a0.y,a0.z,a0.w, a1.x,a1.y,a1.z,a1.w,
                        a2.x,a2.y,a2.z,a2.w, a3.x,a3.y,a3.z,a3.w};
#pragma unroll
        for (int e = 0; e < 16; e++) smf[AS_OFF(0, ak + e, arow)] = av[e];
        cp_wait0_();
    }
    __syncthreads();

    for (int it = 0; it < 8; it++) {
        const int cur = it & 1, nxt = cur ^ 1;
        float4 a0, a1, a2, a3;
        if (it < 7) {
            const int k1 = (it + 1) * GK;
            a0 = *(const float4*)(aptr + k1 + 0);
            a1 = *(const float4*)(aptr + k1 + 4);
            a2 = *(const float4*)(aptr + k1 + 8);
            a3 = *(const float4*)(aptr + k1 + 12);
            const float* bsrc = bptr + (size_t)k1 * N;
            const uint32_t bdst = nxt ? bs_dst1 : bs_dst0;
#pragma unroll
            for (int q = 0; q < 4; q++) cp_async16(bdst + q * 16, bsrc + q * 4);
            cp_commit_();
        }
#pragma unroll
        for (int kk = 0; kk < GK; kk++) {
            float4 av0 = *(const float4*)&smf[AS_OFF(cur, kk, ty * 8)];
            float4 av1 = *(const float4*)&smf[AS_OFF(cur, kk, ty * 8 + 4)];
            ulonglong2 bq0 = *(const ulonglong2*)&smf[BS_OFF(cur, kk, tx * 8)];
            ulonglong2 bq1 = *(const ulonglong2*)&smf[BS_OFF(cur, kk, tx * 8 + 4)];
            u64t bp[4] = {bq0.x, bq0.y, bq1.x, bq1.y};
            float a_[8] = {av0.x, av0.y, av0.z, av0.w, av1.x, av1.y, av1.z, av1.w};
#pragma unroll
            for (int i = 0; i < 8; i++) {
                u64t ad = pack2_(a_[i], a_[i]);
#pragma unroll
                for (int jp = 0; jp < 4; jp++)
                    acc2[i][jp] = fma2_(ad, bp[jp], acc2[i][jp]);
            }
        }
        if (it < 7) {
            float av[16] = {a0.x,a0.y,a0.z,a0.w, a1.x,a1.y,a1.z,a1.w,
                            a2.x,a2.y,a2.z,a2.w, a3.x,a3.y,a3.z,a3.w};
#pragma unroll
            for (int e = 0; e < 16; e++) smf[AS_OFF(nxt, ak + e, arow)] = av[e];
            cp_wait0_();
        }
        __syncthreads();
    }

    float4 bb0 = *(const float4*)&bias[bn + tx * 8];
    float4 bb1 = *(const float4*)&bias[bn + tx * 8 + 4];
    float bb[8] = {bb0.x, bb0.y, bb0.z, bb0.w, bb1.x, bb1.y, bb1.z, bb1.w};
#pragma unroll
    for (int i = 0; i < 8; i++) {
        int m = bm + ty * 8 + i;
        float v[8];
#pragma unroll
        for (int jp = 0; jp < 4; jp++) {
            float lo, hi; unpack2_(acc2[i][jp], lo, hi);
            v[2 * jp] = lo + bb[2 * jp];
            v[2 * jp + 1] = hi + bb[2 * jp + 1];
            if (SIG) { v[2 * jp] = sigmoidf_(v[2 * jp]); v[2 * jp + 1] = sigmoidf_(v[2 * jp + 1]); }
        }
        *(float4*)&out[(size_t)m * N + bn + tx * 8]     = make_float4(v[0], v[1], v[2], v[3]);
        *(float4*)&out[(size_t)m * N + bn + tx * 8 + 4] = make_float4(v[4], v[5], v[6], v[7]);
    }
}

// Fused Gx+Cx kernel (r16, measured 559us): bn-major grid for L2 reuse of A.
__global__ void __launch_bounds__(256, 2) gemm_fused(
    const float* __restrict__ A,
    const float* __restrict__ Wg, const float* __restrict__ bg,
    const float* __restrict__ Wc, const float* __restrict__ bc,
    float* __restrict__ Gx, float* __restrict__ Cx)
{
    extern __shared__ float smf[];
    const int bnG = blockIdx.x;
    const int bm = blockIdx.y * 128;
    if (bnG < 4)
        gemm_body<false>(A, Wg, bg, Gx, 512, bm, bnG * 128, smf);
    else
        gemm_body<false>(A, Wc, bc, Cx, 256, bm, (bnG - 4) * 128, smf);
}

// Projection kernel (exact sigmoid on the output path)
__global__ void __launch_bounds__(256, 2) gemm_proj(
    const float* __restrict__ A, const float* __restrict__ W,
    const float* __restrict__ bias, float* __restrict__ out)
{
    extern __shared__ float smf[];
    gemm_body<true>(A, W, bias, out, 256, blockIdx.y * 128, blockIdx.x * 128, smf);
}

// ---------------------------------------------------------------------------
// mbarrier / DSMEM async-store helpers
// ---------------------------------------------------------------------------
__device__ __forceinline__ uint32_t mapa_(uint32_t saddr, unsigned rank)
{
    uint32_t ra;
    asm volatile("mapa.shared::cluster.u32 %0, %1, %2;" : "=r"(ra) : "r"(saddr), "r"(rank));
    return ra;
}
__device__ __forceinline__ void st_async_tx(uint32_t raddr, float v, uint32_t rmbar)
{
    asm volatile("st.async.shared::cluster.mbarrier::complete_tx::bytes.b32 [%0], %1, [%2];"
                 :: "r"(raddr), "r"(__float_as_uint(v)), "r"(rmbar) : "memory");
}
__device__ __forceinline__ void mbar_init_(uint32_t mbar, uint32_t cnt)
{
    asm volatile("mbarrier.init.shared.b64 [%0], %1;" :: "r"(mbar), "r"(cnt) : "memory");
}
__device__ __forceinline__ void mbar_expect_tx_(uint32_t mbar, uint32_t bytes)
{
    asm volatile("mbarrier.arrive.expect_tx.shared.b64 _, [%0], %1;"
                 :: "r"(mbar), "r"(bytes) : "memory");
}
__device__ __forceinline__ void mbar_wait_parity_(uint32_t mbar, uint32_t parity)
{
    uint32_t done;
    asm volatile(
        "{\n\t.reg .pred p;\n\t"
        "mbarrier.try_wait.parity.acquire.cta.shared::cta.b64 p, [%1], %2;\n\t"
        "selp.b32 %0, 1, 0, p;\n\t}"
        : "=r"(done) : "r"(mbar), "r"(parity) : "memory");
    if (!done) {
        asm volatile(
            "{\n\t.reg .pred P1;\n\t"
            "WL_%=:\n\t"
            "mbarrier.try_wait.parity.acquire.cta.shared::cta.b64 P1, [%0], %1, 0x989680;\n\t"
            "@P1 bra.uni WD_%=;\n\t"
            "bra.uni WL_%=;\n\t"
            "WD_%=:\n\t}"
            :: "r"(mbar), "r"(parity) : "memory");
    }
}
__device__ __forceinline__ void cluster_sync_()
{
    asm volatile("barrier.cluster.arrive.aligned;" ::: "memory");
    asm volatile("barrier.cluster.wait.aligned;" ::: "memory");
}

// SMEM float offsets (keep 8B alignment for all f32x2/mbarrier regions)
#define OFF_WCT 0                  // cand weights transposed [256 cols][66 pad]
#define OFF_H   16896              // h slice [64]
#define OFF_RH  16960              // r*h slice [64]
#define OFF_U   17024              // u slice [64]
#define OFF_GP  17088              // gate partials [4 src][128] (coalesced st.async)
#define OFF_CP  17600              // cand partials [8 src][64]
#define OFF_MB  18112              // 2 mbarriers (2 floats each)
#define SMEM_FLOATS 18120
#define SMEM_BYTES (SMEM_FLOATS * 4)

// ---------------------------------------------------------------------------
// Recurrence — r13 structure (best measured); r17 change: gate sigmoid and
// cand tanh use single-MUFU tanh.approx (sigmoid(x)=0.5+0.5*tanh(x/2)),
// shortening the two serialized transcendental points of the step.
// ---------------------------------------------------------------------------
__global__ void __cluster_dims__(NCTA, 1, 1) __launch_bounds__(RTH, 1)
gru_rec(const float* __restrict__ Wg, const float* __restrict__ Wc)
{
    extern __shared__ float sm[];
    float* sWcT = sm + OFF_WCT;
    float* sh   = sm + OFF_H;
    float* srh  = sm + OFF_RH;
    float* su   = sm + OFF_U;
    float* sgp  = sm + OFF_GP;
    float* scp  = sm + OFF_CP;

    const int tid = threadIdx.x;
    unsigned rank;
    asm("mov.u32 %0, %%cluster_ctarank;" : "=r"(rank));
    const int j = (int)rank;
    const int b = blockIdx.x >> 2;

    const uint32_t gmb = (uint32_t)__cvta_generic_to_shared(sm + OFF_MB);
    const uint32_t cmb = (uint32_t)__cvta_generic_to_shared(sm + OFF_MB + 2);

    if (tid == 0) { mbar_init_(gmb, 1); mbar_init_(cmb, 1); }

    // ---- gate weight registers, packed row-pairs: thread = gate col `tid`,
    //      rows 256 + j*64 + (2i, 2i+1)
    u64t wg2[32];
#pragma unroll
    for (int i = 0; i < 32; i++) {
        float w0 = Wg[(size_t)(256 + j * 64 + 2 * i) * 512 + tid];
        float w1 = Wg[(size_t)(256 + j * 64 + 2 * i + 1) * 512 + tid];
        wg2[i] = pack2_(w0, w1);
    }

    // cand thread mapping
    const int c = tid & 255;
    const int s = tid >> 8;

    // ---- cand weight registers: rows s*32 + (2i, 2i+1), i = 0..7 (16 rows)
    u64t wc2[8];
#pragma unroll
    for (int i = 0; i < 8; i++) {
        int row = 256 + j * 64 + s * 32 + 2 * i;
        wc2[i] = pack2_(Wc[(size_t)row * 256 + c],
                        Wc[(size_t)(row + 1) * 256 + c]);
    }

    // ---- stage candidate weights transposed: sWcT[cc*66 + r] = Wc_h[row r, col cc]
    for (int idx = tid; idx < 64 * 256; idx += RTH) {
        int cc = idx & 255, r = idx >> 8;
        sWcT[cc * 66 + r] = Wc[(size_t)(256 + j * 64 + r) * 256 + cc];
    }
    if (tid < 64) sh[tid] = 0.f;
    __syncthreads();
    cluster_sync_();   // mbarriers + weights visible cluster-wide before any st.async

    const float* gGx = g_Gx + (size_t)b * Tt * Gg;
    const float* gCx = g_Cx + (size_t)b * Tt * Hh;
    float* grnn = g_rnn + (size_t)b * Tt * Hh;

    // gate column -> owner rank + local slot; precompute remote addrs (loop-invariant)
    const int gk = (tid < 256) ? (tid >> 6) : ((tid >> 6) & 3);
    const int gl = (tid < 256) ? (tid & 63) : (64 + (tid & 63));
    const uint32_t gp_rem  = mapa_((uint32_t)__cvta_generic_to_shared(&sgp[j * 128 + gl]), (unsigned)gk);
    const uint32_t gmb_rem = mapa_(gmb, (unsigned)gk);

    // cand: thread = (col c, row-half s)
    const int ck = c >> 6;
    const uint32_t cp_rem  = mapa_((uint32_t)__cvta_generic_to_shared(&scp[(j * 2 + s) * 64 + (c & 63)]), (unsigned)ck);
    const uint32_t cmb_rem = mapa_(cmb, (unsigned)ck);
    const float* wcbase = sWcT + c * 66 + s * 32;
    const float* rhbase = srh + s * 32;

    const int gxcol = (tid < 64) ? (j * 64 + tid) : (256 + j * 64 + (tid - 64));

    float gx = (tid < 128) ? gGx[gxcol] : 0.f;
    float cx = (tid < 64)  ? gCx[j * 64 + tid] : 0.f;

    for (int t = 0; t < Tt; t++) {
        const uint32_t ph = (uint32_t)(t & 1);
        if (tid == 0) mbar_expect_tx_(gmb, NCTA * 128 * 4);

        // ===== gate partial GEMV (64 own rows x 1 col), FFMA2, 2 chains =====
        {
            u64t accA = 0ull, accB = 0ull;
            const u64t* hp2 = (const u64t*)sh;
#pragma unroll
            for (int i = 0; i < 16; i++) {
                accA = fma2_(hp2[2 * i],     wg2[2 * i],     accA);
                accB = fma2_(hp2[2 * i + 1], wg2[2 * i + 1], accB);
            }
            u64t acc2 = add2_(accA, accB);
            float lo, hi; unpack2_(acc2, lo, hi);
            st_async_tx(gp_rem, lo + hi, gmb_rem);
        }
        // only the consumers of gate partials need the acquire-wait;
        // everyone else is ordered by the __syncthreads below
        if (tid < 128) mbar_wait_parity_(gmb, ph);
        if (tid == 0) mbar_expect_tx_(cmb, NCTA * 128 * 4);

        // ===== gate reduce + r*h / u (local), single-MUFU sigmoid ===========
        if (tid < 128) {
            float sv = gx + sgp[tid] + sgp[128 + tid] + sgp[256 + tid] + sgp[384 + tid];
            float val = sigmoid_ap(sv);
            if (tid < 64) srh[tid] = val * sh[tid];
            else          su[tid - 64] = val;
        }
        if (tid < 128 && t + 1 < Tt)
            gx = gGx[(size_t)(t + 1) * Gg + gxcol];          // prefetch
        __syncthreads();   // srh ready for all threads

        // ===== cand partial GEMV (32 rows x 1 col), FFMA2:
        //       rows 0..15 from REGISTER weights, rows 16..31 from smem ======
        {
            u64t accA = 0ull, accB = 0ull;
            const u64t* rp2 = (const u64t*)rhbase;
            const u64t* wp2 = (const u64t*)wcbase;
#pragma unroll
            for (int i = 0; i < 8; i++) {
                accA = fma2_(rp2[i],     wc2[i],     accA);   // reg half
                accB = fma2_(rp2[8 + i], wp2[8 + i], accB);   // smem half
            }
            u64t acc2 = add2_(accA, accB);
            float lo, hi; unpack2_(acc2, lo, hi);
            st_async_tx(cp_rem, lo + hi, cmb_rem);
        }
        if (tid < 64) mbar_wait_parity_(cmb, ph);           // cand consumers only

        // ===== cand reduce + h update (all local), single-MUFU tanh =========
        if (tid < 64) {
            float cc = cx;
#pragma unroll
            for (int m = 0; m < 8; m++) cc += scp[m * 64 + tid];
            float cv = tanh_ap(cc);
            float u = su[tid];
            float hn = u * sh[tid] + (1.f - u) * cv;
            sh[tid] = hn;
            grnn[(size_t)t * Hh + j * 64 + tid] = hn;
        }
        if (tid < 64 && t + 1 < Tt)
            cx = gCx[(size_t)(t + 1) * Hh + j * 64 + tid];   // prefetch
        __syncthreads();   // sh update visible before next gate GEMV
    }
    cluster_sync_();       // keep peers resident until all deliveries consumed
}

// ---------------------------------------------------------------------------
extern "C" void kernel_launch(void* const* d_in, const int* in_sizes, int n_in,
                              void* d_out, int out_size)
{
    const float* x  = (const float*)d_in[0];
    const float* Wg = (const float*)d_in[1];
    const float* bg = (const float*)d_in[2];
    const float* Wc = (const float*)d_in[3];
    const float* bc = (const float*)d_in[4];
    const float* Wp = (const float*)d_in[5];
    const float* bp = (const float*)d_in[6];
    float* out = (float*)d_out;

    float *pGx = nullptr, *pCx = nullptr, *prnn = nullptr;
    cudaGetSymbolAddress((void**)&pGx, g_Gx);
    cudaGetSymbolAddress((void**)&pCx, g_Cx);
    cudaGetSymbolAddress((void**)&prnn, g_rnn);
    cudaFuncSetAttribute(gru_rec, cudaFuncAttributeMaxDynamicSharedMemorySize, SMEM_BYTES);
    cudaFuncSetAttribute(gemm_fused, cudaFuncAttributeMaxDynamicSharedMemorySize, GEMM_SMEM_BYTES);
    cudaFuncSetAttribute(gemm_proj,  cudaFuncAttributeMaxDynamicSharedMemorySize, GEMM_SMEM_BYTES);

    // Fused x-projections (x read once; bn-major grid for L2 reuse of A)
    gemm_fused<<<dim3(6, 512), 256, GEMM_SMEM_BYTES>>>(x, Wg, bg, Wc, bc, pGx, pCx);

    // Sequential recurrence: 32 clusters x 4 CTAs, 1 batch per cluster
    gru_rec<<<128, RTH, SMEM_BYTES>>>(Wg, Wc);

    // Projection + sigmoid
    gemm_proj<<<dim3(2, 512), 256, GEMM_SMEM_BYTES>>>(prnn, Wp, bp, out);
}